// round 4
// baseline (speedup 1.0000x reference)
#include <cuda_runtime.h>

#define FULL 0xffffffffu
typedef unsigned long long u64;

// ---------- packed f32x2 helpers ----------
__device__ __forceinline__ u64 pk(float lo, float hi) {
    u64 r; asm("mov.b64 %0, {%1,%2};" : "=l"(r) : "f"(lo), "f"(hi)); return r;
}
__device__ __forceinline__ void upk(u64 a, float& lo, float& hi) {
    asm("mov.b64 {%0,%1}, %2;" : "=f"(lo), "=f"(hi) : "l"(a));
}
__device__ __forceinline__ u64 fma2(u64 a, u64 b, u64 c) {
    u64 d; asm("fma.rn.f32x2 %0, %1, %2, %3;" : "=l"(d) : "l"(a), "l"(b), "l"(c)); return d;
}
__device__ __forceinline__ u64 mul2(u64 a, u64 b) {
    u64 d; asm("mul.rn.f32x2 %0, %1, %2;" : "=l"(d) : "l"(a), "l"(b)); return d;
}
__device__ __forceinline__ u64 add2(u64 a, u64 b) {
    u64 d; asm("add.rn.f32x2 %0, %1, %2;" : "=l"(d) : "l"(a), "l"(b)); return d;
}

// Per gate g = layer*8+wire: 8 duplicated-packed constants of fused weight
// matrix C = Rz*Ry*Rx (SU(2) first row):
//   [0]=(C00r,C00r) [1]=(C00i,C00i) [2]=(C01r,C01r) [3]=(C01i,C01i)
//   [4]=-[0] [5]=-[1] [6]=-[2] [7]=-[3]
__device__ u64 g_G[48 * 8];

__global__ void precompute_G(const float* __restrict__ w) {
    int tid = threadIdx.x;
    if (tid >= 48) return;
    float c0, s0, c1, s1, cz, sz;
    sincosf(0.5f * w[tid * 3 + 0], &s0, &c0);   // Rx
    sincosf(0.5f * w[tid * 3 + 1], &s1, &c1);   // Ry
    sincosf(0.5f * w[tid * 3 + 2], &sz, &cz);   // Rz
    float A00r = c1 * c0,  A00i = s1 * s0;
    float A01r = -s1 * c0, A01i = -c1 * s0;
    float C00r = cz * A00r + sz * A00i;
    float C00i = cz * A00i - sz * A00r;
    float C01r = cz * A01r + sz * A01i;
    float C01i = cz * A01i - sz * A01r;
    u64* G = &g_G[tid * 8];
    G[0] = pk(C00r, C00r);   G[1] = pk(C00i, C00i);
    G[2] = pk(C01r, C01r);   G[3] = pk(C01i, C01i);
    G[4] = pk(-C00r, -C00r); G[5] = pk(-C00i, -C00i);
    G[6] = pk(-C01r, -C01r); G[7] = pk(-C01i, -C01i);
}

// Two batch elements per warp: element A in lo half of every f32x2, element B
// in hi half. Lane holds 8 complex amplitudes per element: amp index
// n = lane*8 + t; lane bits 4..0 = wires 0..4, t bits 2..0 = wires 5,6,7.
__global__ void __launch_bounds__(256, 4) qnn_kernel(const float4* __restrict__ x4,
                                                     float* __restrict__ out, int NW2) {
    __shared__ u64 sG[48 * 8];
    for (int k = threadIdx.x; k < 48 * 8; k += blockDim.x) sG[k] = g_G[k];
    __syncthreads();

    int gw = (blockIdx.x * blockDim.x + threadIdx.x) >> 5;  // warp id = element pair
    int lane = threadIdx.x & 31;
    if (gw >= NW2) return;

    float4 xx = x4[gw];   // (x0A, x1A, x0B, x1B)
    float seA, ceA, soA, coA, seB, ceB, soB, coB;
    sincosf(0.5f * xx.x, &seA, &ceA);
    sincosf(0.5f * xx.y, &soA, &coA);
    sincosf(0.5f * xx.z, &seB, &ceB);
    sincosf(0.5f * xx.w, &soB, &coB);
    const u64 ce2 = pk(ceA, ceB), se2 = pk(seA, seB);
    const u64 co2 = pk(coA, coB), so2 = pk(soA, soB);
    const u64 n1 = pk(-1.f, -1.f);

    u64 sr[8], si[8];

    // gate-constant builder: M = C * E(x), packed across the two elements.
    // outputs: M00r,M00i,nM00i,M01r,nM01r,M01i,nM01i
#define GCONSTS(gate, wire)                                                  \
    const u64* G = &sG[(gate) * 8];                                          \
    u64 M00r, M00i, M01r, M01i;                                              \
    if (((wire) & 1) == 0) { /* RX */                                        \
        M00r = fma2(ce2, G[0], mul2(se2, G[3]));                             \
        M00i = fma2(ce2, G[1], mul2(se2, G[6]));                             \
        M01r = fma2(ce2, G[2], mul2(se2, G[1]));                             \
        M01i = fma2(ce2, G[3], mul2(se2, G[4]));                             \
    } else { /* RY */                                                        \
        M00r = fma2(co2, G[0], mul2(so2, G[2]));                             \
        M00i = fma2(co2, G[1], mul2(so2, G[3]));                             \
        M01r = fma2(co2, G[2], mul2(so2, G[4]));                             \
        M01i = fma2(co2, G[3], mul2(so2, G[5]));                             \
    }                                                                        \
    u64 nM00i = mul2(n1, M00i);                                              \
    u64 nM01r = mul2(n1, M01r);                                              \
    u64 nM01i = mul2(n1, M01i);

    // ---------- layer 0: product state directly from |0..0> ----------
    {
        u64 cr2, ci2;
        // wires 0..4 prefix over lane bits (column 0 of M: g0=(M00r,M00i), g1=(-M01r,M01i))
        {
            GCONSTS(0, 0);
            bool b = (lane >> 4) & 1;
            cr2 = b ? nM01r : M00r;
            ci2 = b ? M01i : M00i;
        }
#pragma unroll
        for (int wv = 1; wv < 5; wv++) {
            GCONSTS(wv, wv);
            bool b = (lane >> (4 - wv)) & 1;
            u64 fr2  = b ? nM01r : M00r;
            u64 fi2  = b ? M01i  : M00i;
            u64 nfi2 = b ? nM01i : nM00i;
            u64 nr = fma2(cr2, fr2, mul2(ci2, nfi2));
            u64 ni = fma2(cr2, fi2, mul2(ci2, fr2));
            cr2 = nr; ci2 = ni;
        }
        // wire 5 (t bit2)
        u64 a0r, a0i, a1r, a1i;
        {
            GCONSTS(5, 5);
            a0r = fma2(cr2, M00r,  mul2(ci2, nM00i));
            a0i = fma2(cr2, M00i,  mul2(ci2, M00r));
            a1r = fma2(cr2, nM01r, mul2(ci2, nM01i));
            a1i = fma2(cr2, M01i,  mul2(ci2, nM01r));
        }
        // wire 6 (t bit1)
        u64 er[4], ei[4];
        {
            GCONSTS(6, 6);
            er[0] = fma2(a0r, M00r,  mul2(a0i, nM00i));
            ei[0] = fma2(a0r, M00i,  mul2(a0i, M00r));
            er[1] = fma2(a0r, nM01r, mul2(a0i, nM01i));
            ei[1] = fma2(a0r, M01i,  mul2(a0i, nM01r));
            er[2] = fma2(a1r, M00r,  mul2(a1i, nM00i));
            ei[2] = fma2(a1r, M00i,  mul2(a1i, M00r));
            er[3] = fma2(a1r, nM01r, mul2(a1i, nM01i));
            ei[3] = fma2(a1r, M01i,  mul2(a1i, nM01r));
        }
        // wire 7 (t bit0)
        {
            GCONSTS(7, 7);
#pragma unroll
            for (int t = 0; t < 8; t++) {
                int e = t >> 1;
                if ((t & 1) == 0) {
                    sr[t] = fma2(er[e], M00r, mul2(ei[e], nM00i));
                    si[t] = fma2(er[e], M00i, mul2(ei[e], M00r));
                } else {
                    sr[t] = fma2(er[e], nM01r, mul2(ei[e], nM01i));
                    si[t] = fma2(er[e], M01i,  mul2(ei[e], nM01r));
                }
            }
        }
    }

    // CNOT chain (shared by all layers)
#define CNOT_CHAIN()                                                          \
    {                                                                         \
        int src = lane;                                                       \
        src ^= (src >> 1) & 1;                                                \
        src ^= (src >> 1) & 2;                                                \
        src ^= (src >> 1) & 4;                                                \
        src ^= (src >> 1) & 8;                                                \
        _Pragma("unroll")                                                     \
        for (int t = 0; t < 8; t++) {                                         \
            sr[t] = __shfl_sync(FULL, sr[t], src);                            \
            si[t] = __shfl_sync(FULL, si[t], src);                            \
        }                                                                     \
        bool ctl = (lane & 1) != 0;                                           \
        _Pragma("unroll")                                                     \
        for (int k = 0; k < 4; k++) {                                         \
            u64 a = sr[k], b = sr[k + 4];                                     \
            sr[k] = ctl ? b : a; sr[k + 4] = ctl ? a : b;                     \
            u64 c = si[k], d = si[k + 4];                                     \
            si[k] = ctl ? d : c; si[k + 4] = ctl ? c : d;                     \
        }                                                                     \
        { u64 t_;                                                             \
          t_ = sr[4]; sr[4] = sr[6]; sr[6] = t_;                              \
          t_ = si[4]; si[4] = si[6]; si[6] = t_;                              \
          t_ = sr[5]; sr[5] = sr[7]; sr[7] = t_;                              \
          t_ = si[5]; si[5] = si[7]; si[7] = t_; }                            \
        { u64 t_;                                                             \
          t_ = sr[2]; sr[2] = sr[3]; sr[3] = t_;                              \
          t_ = si[2]; si[2] = si[3]; si[3] = t_;                              \
          t_ = sr[6]; sr[6] = sr[7]; sr[7] = t_;                              \
          t_ = si[6]; si[6] = si[7]; si[7] = t_; }                            \
    }

    CNOT_CHAIN();

    // ---------- layers 1..5 ----------
#pragma unroll 1
    for (int layer = 1; layer < 6; layer++) {
#pragma unroll
        for (int wire = 0; wire < 8; wire++) {
            GCONSTS(layer * 8 + wire, wire);
            if (wire < 5) {
                // lane-level butterfly via u64 shfl.xor
                const int lm = 1 << (4 - wire);
                bool neg = (lane & lm) != 0;
                u64 Pi2  = neg ? nM00i : M00i;
                u64 nPi2 = neg ? M00i  : nM00i;
                u64 Qr2  = neg ? nM01r : M01r;
#pragma unroll
                for (int t = 0; t < 8; t++) {
                    u64 osr = __shfl_xor_sync(FULL, sr[t], lm);
                    u64 osi = __shfl_xor_sync(FULL, si[t], lm);
                    u64 nr = fma2(M00r, sr[t], fma2(nPi2, si[t], fma2(Qr2, osr, mul2(nM01i, osi))));
                    u64 ni = fma2(Pi2,  sr[t], fma2(M00r, si[t], fma2(M01i, osr, mul2(Qr2, osi))));
                    sr[t] = nr; si[t] = ni;
                }
            } else {
                // register-level butterfly: wire5 stride 4, wire6 stride 2, wire7 stride 1
                const int off = (wire == 5) ? 4 : ((wire == 6) ? 2 : 1);
#pragma unroll
                for (int t = 0; t < 8; t++) {
                    if (t & off) continue;
                    const int u = t | off;
                    u64 ar = sr[t], ai = si[t], br = sr[u], bi = si[u];
                    sr[t] = fma2(M00r,  ar, fma2(nM00i, ai, fma2(M01r, br, mul2(nM01i, bi))));
                    si[t] = fma2(M00i,  ar, fma2(M00r,  ai, fma2(M01i, br, mul2(M01r,  bi))));
                    sr[u] = fma2(nM01r, ar, fma2(nM01i, ai, fma2(M00r, br, mul2(M00i,  bi))));
                    si[u] = fma2(M01i,  ar, fma2(nM01r, ai, fma2(nM00i, br, mul2(M00r, bi))));
                }
            }
        }
        CNOT_CHAIN();
    }

    // ---------- expectation values (packed over both elements) ----------
    u64 p[8];
#pragma unroll
    for (int t = 0; t < 8; t++) p[t] = fma2(sr[t], sr[t], mul2(si[t], si[t]));

    u64 q01 = add2(p[0], p[1]), q23 = add2(p[2], p[3]);
    u64 q45 = add2(p[4], p[5]), q67 = add2(p[6], p[7]);
    u64 h0 = add2(q01, q23), h1 = add2(q45, q67);
    u64 tot = add2(h0, h1), ntot = mul2(n1, tot);

    u64 ev[8];
#pragma unroll
    for (int i = 0; i < 5; i++)
        ev[i] = (lane & (1 << (4 - i))) ? ntot : tot;
    ev[5] = fma2(n1, h1, h0);
    ev[6] = fma2(n1, add2(q23, q67), add2(q01, q45));
    {
        u64 e0 = add2(add2(p[0], p[2]), add2(p[4], p[6]));
        u64 o0 = add2(add2(p[1], p[3]), add2(p[5], p[7]));
        ev[7] = fma2(n1, o0, e0);
    }

#pragma unroll
    for (int off = 16; off > 0; off >>= 1) {
#pragma unroll
        for (int i = 0; i < 8; i++)
            ev[i] = add2(ev[i], __shfl_xor_sync(FULL, ev[i], off));
    }

    if (lane == 0) {
        const u64 pi2 = pk(3.14159265358979f, 3.14159265358979f);
        float lo[8], hi[8];
#pragma unroll
        for (int i = 0; i < 8; i++) {
            u64 s = mul2(pi2, ev[i]);
            upk(s, lo[i], hi[i]);
        }
        float4* o4 = (float4*)out;   // element A at row 2*gw, element B at 2*gw+1
        o4[gw * 4 + 0] = make_float4(lo[0], lo[1], lo[2], lo[3]);
        o4[gw * 4 + 1] = make_float4(lo[4], lo[5], lo[6], lo[7]);
        o4[gw * 4 + 2] = make_float4(hi[0], hi[1], hi[2], hi[3]);
        o4[gw * 4 + 3] = make_float4(hi[4], hi[5], hi[6], hi[7]);
    }
#undef GCONSTS
#undef CNOT_CHAIN
}

extern "C" void kernel_launch(void* const* d_in, const int* in_sizes, int n_in,
                              void* d_out, int out_size) {
    const float* x = (const float*)d_in[0];   // [B, 2]
    const float* w = (const float*)d_in[1];   // [6, 8, 3]
    float* out = (float*)d_out;               // [B, 8]
    int B = in_sizes[0] / 2;
    int NW2 = B / 2;                          // element pairs (B is even)

    precompute_G<<<1, 64>>>(w);
    int threads = 256;
    int blocks = (NW2 * 32 + threads - 1) / threads;
    qnn_kernel<<<blocks, threads>>>((const float4*)x, out, NW2);
}

// round 6
// speedup vs baseline: 1.1195x; 1.1195x over previous
#include <cuda_runtime.h>

#define FULL 0xffffffffu
typedef unsigned long long u64;

// ---------- packed f32x2 helpers ----------
__device__ __forceinline__ u64 pk(float lo, float hi) {
    u64 r; asm("mov.b64 %0, {%1,%2};" : "=l"(r) : "f"(lo), "f"(hi)); return r;
}
__device__ __forceinline__ u64 pk2(float v) { return pk(v, v); }
__device__ __forceinline__ void upk(u64 a, float& lo, float& hi) {
    asm("mov.b64 {%0,%1}, %2;" : "=f"(lo), "=f"(hi) : "l"(a));
}
__device__ __forceinline__ u64 fma2(u64 a, u64 b, u64 c) {
    u64 d; asm("fma.rn.f32x2 %0, %1, %2, %3;" : "=l"(d) : "l"(a), "l"(b), "l"(c)); return d;
}
__device__ __forceinline__ u64 mul2(u64 a, u64 b) {
    u64 d; asm("mul.rn.f32x2 %0, %1, %2;" : "=l"(d) : "l"(a), "l"(b)); return d;
}
__device__ __forceinline__ u64 swp(u64 a) { float l, h; upk(a, l, h); return pk(h, l); }
__device__ __forceinline__ u64 shfx(u64 a, int m) {
    float l, h; upk(a, l, h);
    return pk(__shfl_xor_sync(FULL, l, m), __shfl_xor_sync(FULL, h, m));
}
__device__ __forceinline__ u64 shfi(u64 a, int s) {
    float l, h; upk(a, l, h);
    return pk(__shfl_sync(FULL, l, s), __shfl_sync(FULL, h, s));
}

// Per gate (layer*8+wire): fused weight matrix C = Rz*Ry*Rx (SU(2) first row):
// (C00r, C00i, C01r, C01i)
__device__ float4 g_Gf[48];

__global__ void precompute_G(const float* __restrict__ w) {
    int tid = threadIdx.x;
    if (tid >= 48) return;
    float c0, s0, c1, s1, cz, sz;
    sincosf(0.5f * w[tid * 3 + 0], &s0, &c0);   // Rx
    sincosf(0.5f * w[tid * 3 + 1], &s1, &c1);   // Ry
    sincosf(0.5f * w[tid * 3 + 2], &sz, &cz);   // Rz
    float A00r = c1 * c0,  A00i = s1 * s0;
    float A01r = -s1 * c0, A01i = -c1 * s0;
    float C00r = cz * A00r + sz * A00i;
    float C00i = cz * A00i - sz * A00r;
    float C01r = cz * A01r + sz * A01i;
    float C01i = cz * A01i - sz * A01r;
    g_Gf[tid] = make_float4(C00r, C00i, C01r, C01i);
}

// One warp per batch element. Amplitude n: lane bits 4..0 = n bits 7..3
// (wires 0..4), reg index t bits 2..0 = n bits 2..0 (wires 5,6,7).
// State packed SoA along t-bit0 (wire7): pr[j]=(re[2j],re[2j+1]), pi[j] same.
__global__ void __launch_bounds__(128, 10) qnn_kernel(const float* __restrict__ x,
                                                      float* __restrict__ out, int B) {
    __shared__ float4 sG[48];
    if (threadIdx.x < 48) sG[threadIdx.x] = g_Gf[threadIdx.x];
    __syncthreads();

    int warp = (blockIdx.x * blockDim.x + threadIdx.x) >> 5;
    int lane = threadIdx.x & 31;
    if (warp >= B) return;

    float se, ce, so, co;
    __sincosf(0.5f * x[2 * warp + 0], &se, &ce);  // RX enc (even wires)
    __sincosf(0.5f * x[2 * warp + 1], &so, &co);  // RY enc (odd wires)
    u64 ce2 = pk2(ce), se2 = pk2(se), co2 = pk2(co), so2 = pk2(so), nso2 = pk2(-so);

    // Fused gate matrix M = C*E(x): packed m00=(m00r,m00i), m01=(m01r,m01i).
#define GATE_M(g, wire, m00p, m01p)                                        \
    {                                                                      \
        float4 Cg = sG[g];                                                 \
        u64 Gx = pk(Cg.x, Cg.y);   /* (C00r,C00i) */                       \
        u64 Gy = pk(Cg.z, Cg.w);   /* (C01r,C01i) */                       \
        u64 Gz = pk(Cg.w, -Cg.z);  /* (C01i,-C01r) */                      \
        u64 Gw = pk(Cg.y, -Cg.x);  /* (C00i,-C00r) */                      \
        if (((wire) & 1) == 0) {   /* RX */                                \
            m00p = fma2(ce2, Gx, mul2(se2, Gz));                           \
            m01p = fma2(ce2, Gy, mul2(se2, Gw));                           \
        } else {                   /* RY */                                \
            m00p = fma2(co2, Gx, mul2(so2, Gy));                           \
            m01p = fma2(co2, Gy, mul2(nso2, Gx));                          \
        }                                                                  \
    }

    u64 pr[4], pi[4];

    // ---------- layer 0: product state built directly from |0..0> ----------
    {
        float g0r[8], g0i[8], g1r[8], g1i[8];   // column 0: m00 and m10=-conj(m01)
#pragma unroll
        for (int wv = 0; wv < 8; wv++) {
            u64 m00p, m01p;
            GATE_M(wv, wv, m00p, m01p);
            float r0, i0, r1, i1;
            upk(m00p, r0, i0); upk(m01p, r1, i1);
            g0r[wv] = r0;  g0i[wv] = i0;
            g1r[wv] = -r1; g1i[wv] = i1;
        }
        float cr = 1.f, ci = 0.f;
#pragma unroll
        for (int wv = 0; wv < 5; wv++) {
            bool b = (lane >> (4 - wv)) & 1;
            float fr = b ? g1r[wv] : g0r[wv];
            float fi = b ? g1i[wv] : g0i[wv];
            float nr = cr * fr - ci * fi;
            float ni = cr * fi + ci * fr;
            cr = nr; ci = ni;
        }
        float ar[8], ai[8];
        {
            float d0r = cr * g0r[5] - ci * g0i[5], d0i = cr * g0i[5] + ci * g0r[5];
            float d1r = cr * g1r[5] - ci * g1i[5], d1i = cr * g1i[5] + ci * g1r[5];
            float e0r[4], e0i[4];
            e0r[0] = d0r * g0r[6] - d0i * g0i[6]; e0i[0] = d0r * g0i[6] + d0i * g0r[6];
            e0r[1] = d0r * g1r[6] - d0i * g1i[6]; e0i[1] = d0r * g1i[6] + d0i * g1r[6];
            e0r[2] = d1r * g0r[6] - d1i * g0i[6]; e0i[2] = d1r * g0i[6] + d1i * g0r[6];
            e0r[3] = d1r * g1r[6] - d1i * g1i[6]; e0i[3] = d1r * g1i[6] + d1i * g1r[6];
#pragma unroll
            for (int t = 0; t < 8; t++) {
                int e = t >> 1;
                bool b7 = t & 1;
                float fr = b7 ? g1r[7] : g0r[7];
                float fi = b7 ? g1i[7] : g0i[7];
                ar[t] = e0r[e] * fr - e0i[e] * fi;
                ai[t] = e0r[e] * fi + e0i[e] * fr;
            }
        }
#pragma unroll
        for (int j = 0; j < 4; j++) {
            pr[j] = pk(ar[2 * j], ar[2 * j + 1]);
            pi[j] = pk(ai[2 * j], ai[2 * j + 1]);
        }
    }

    // lane permutation source for the composed CNOT(0,1)..CNOT(3,4) chain
    int src = lane;
    src ^= (src >> 1) & 1;
    src ^= (src >> 1) & 2;
    src ^= (src >> 1) & 4;
    src ^= (src >> 1) & 8;
    const bool ctl45 = (lane & 1) != 0;

    // layer-0 CNOT chain + layers 1..5 (gates + CNOTs)
#pragma unroll
    for (int layer = 0; layer < 6; layer++) {
        if (layer > 0) {
#pragma unroll
            for (int wire = 0; wire < 8; wire++) {
                u64 m00p, m01p;
                GATE_M(layer * 8 + wire, wire, m00p, m01p);
                float m00r, m00i, m01r, m01i;
                upk(m00p, m00r, m00i); upk(m01p, m01r, m01i);

                if (wire < 5) {
                    // lane-level butterfly via shfl.xor
                    const int lm = 1 << (4 - wire);
                    bool neg = (lane & lm) != 0;
                    float Piv = neg ? -m00i : m00i;
                    float Qrv = neg ? -m01r : m01r;
                    u64 Pr2 = pk2(m00r), Pi2 = pk2(Piv), nPi2 = pk2(-Piv);
                    u64 Qr2 = pk2(Qrv), Qi2 = pk2(m01i), nQi2 = pk2(-m01i);
#pragma unroll
                    for (int j = 0; j < 4; j++) {
                        u64 opr = shfx(pr[j], lm);
                        u64 opi = shfx(pi[j], lm);
                        u64 nr = fma2(Pr2, pr[j], fma2(nPi2, pi[j], fma2(Qr2, opr, mul2(nQi2, opi))));
                        u64 ni = fma2(Pi2, pr[j], fma2(Pr2, pi[j], fma2(Qi2, opr, mul2(Qr2, opi))));
                        pr[j] = nr; pi[j] = ni;
                    }
                } else if (wire < 7) {
                    // inter-register packed butterfly (wire5: stride 2; wire6: stride 1)
                    u64 r00 = pk2(m00r), i00 = pk2(m00i), ni00 = pk2(-m00i);
                    u64 r01 = pk2(m01r), nr01 = pk2(-m01r), i01 = pk2(m01i), ni01 = pk2(-m01i);
                    const int off = (wire == 5) ? 2 : 1;
#pragma unroll
                    for (int j = 0; j < 4; j++) {
                        if (j & off) continue;
                        int k = j | off;
                        u64 pA = pr[j], qA = pi[j], pB = pr[k], qB = pi[k];
                        pr[j] = fma2(r00, pA, fma2(ni00, qA, fma2(r01, pB, mul2(ni01, qB))));
                        pi[j] = fma2(i00, pA, fma2(r00, qA, fma2(i01, pB, mul2(r01, qB))));
                        pr[k] = fma2(nr01, pA, fma2(ni01, qA, fma2(r00, pB, mul2(i00, qB))));
                        pi[k] = fma2(i01, pA, fma2(nr01, qA, fma2(ni00, pB, mul2(r00, qB))));
                    }
                } else {
                    // wire7: intra-register butterfly with half-swaps
                    u64 A = pk2(m00r);
                    u64 Bc = pk(m01r, -m01r);
                    u64 Cc = pk(-m00i, m00i);
                    u64 D = pk2(-m01i);
                    u64 E = pk(m00i, -m00i);
                    u64 F = pk2(m01i);
#pragma unroll
                    for (int j = 0; j < 4; j++) {
                        u64 spr = swp(pr[j]), spi = swp(pi[j]);
                        u64 nr = fma2(A, pr[j], fma2(Bc, spr, fma2(Cc, pi[j], mul2(D, spi))));
                        u64 ni = fma2(E, pr[j], fma2(F, spr, fma2(A, pi[j], mul2(Bc, spi))));
                        pr[j] = nr; pi[j] = ni;
                    }
                }
            }
        }

        // ---- CNOT chain ----
        // CNOT(0,1)..CNOT(3,4): composed lane permutation
#pragma unroll
        for (int j = 0; j < 4; j++) {
            pr[j] = shfi(pr[j], src);
            pi[j] = shfi(pi[j], src);
        }
        // CNOT(4,5): control lane bit0, target reg bit2
#pragma unroll
        for (int k = 0; k < 2; k++) {
            u64 a = pr[k], b = pr[k + 2];
            pr[k] = ctl45 ? b : a; pr[k + 2] = ctl45 ? a : b;
            u64 c = pi[k], d = pi[k + 2];
            pi[k] = ctl45 ? d : c; pi[k + 2] = ctl45 ? c : d;
        }
        // CNOT(5,6): swap reg pair 2<->3 (t: 4<->6, 5<->7)  [free rename — loop unrolled]
        {
            u64 t;
            t = pr[2]; pr[2] = pr[3]; pr[3] = t;
            t = pi[2]; pi[2] = pi[3]; pi[3] = t;
        }
        // CNOT(6,7): swap halves of regs 1 and 3 (t: 2<->3, 6<->7)
        pr[1] = swp(pr[1]); pr[3] = swp(pr[3]);
        pi[1] = swp(pi[1]); pi[3] = swp(pi[3]);
    }

    // ---------- expectation values ----------
    float p[8];
#pragma unroll
    for (int j = 0; j < 4; j++) {
        u64 pp = fma2(pr[j], pr[j], mul2(pi[j], pi[j]));
        upk(pp, p[2 * j], p[2 * j + 1]);
    }

    float ev[8];
    float tot = ((p[0] + p[1]) + (p[2] + p[3])) + ((p[4] + p[5]) + (p[6] + p[7]));
#pragma unroll
    for (int i = 0; i < 5; i++)
        ev[i] = (lane & (1 << (4 - i))) ? -tot : tot;
    ev[5] = (p[0] + p[1] + p[2] + p[3]) - (p[4] + p[5] + p[6] + p[7]);
    ev[6] = (p[0] + p[1] + p[4] + p[5]) - (p[2] + p[3] + p[6] + p[7]);
    ev[7] = (p[0] + p[2] + p[4] + p[6]) - (p[1] + p[3] + p[5] + p[7]);

#pragma unroll
    for (int off = 16; off > 0; off >>= 1) {
#pragma unroll
        for (int i = 0; i < 8; i++)
            ev[i] += __shfl_xor_sync(FULL, ev[i], off);
    }

    if (lane == 0) {
        const float PI = 3.14159265358979f;
        ((float4*)out)[warp * 2 + 0] = make_float4(ev[0] * PI, ev[1] * PI, ev[2] * PI, ev[3] * PI);
        ((float4*)out)[warp * 2 + 1] = make_float4(ev[4] * PI, ev[5] * PI, ev[6] * PI, ev[7] * PI);
    }
#undef GATE_M
}

extern "C" void kernel_launch(void* const* d_in, const int* in_sizes, int n_in,
                              void* d_out, int out_size) {
    const float* x = (const float*)d_in[0];   // [B, 2]
    const float* w = (const float*)d_in[1];   // [6, 8, 3]
    float* out = (float*)d_out;               // [B, 8]
    int B = in_sizes[0] / 2;

    precompute_G<<<1, 64>>>(w);
    int threads = 128;
    int blocks = (B * 32 + threads - 1) / threads;
    qnn_kernel<<<blocks, threads>>>(x, out, B);
}

// round 7
// speedup vs baseline: 1.1209x; 1.0013x over previous
#include <cuda_runtime.h>

#define FULL 0xffffffffu
typedef unsigned long long u64;

// ---------- packed f32x2 helpers ----------
__device__ __forceinline__ u64 pk(float lo, float hi) {
    u64 r; asm("mov.b64 %0, {%1,%2};" : "=l"(r) : "f"(lo), "f"(hi)); return r;
}
__device__ __forceinline__ u64 pk2(float v) { return pk(v, v); }
__device__ __forceinline__ void upk(u64 a, float& lo, float& hi) {
    asm("mov.b64 {%0,%1}, %2;" : "=f"(lo), "=f"(hi) : "l"(a));
}
__device__ __forceinline__ u64 fma2(u64 a, u64 b, u64 c) {
    u64 d; asm("fma.rn.f32x2 %0, %1, %2, %3;" : "=l"(d) : "l"(a), "l"(b), "l"(c)); return d;
}
__device__ __forceinline__ u64 mul2(u64 a, u64 b) {
    u64 d; asm("mul.rn.f32x2 %0, %1, %2;" : "=l"(d) : "l"(a), "l"(b)); return d;
}
__device__ __forceinline__ u64 swp(u64 a) { float l, h; upk(a, l, h); return pk(h, l); }
__device__ __forceinline__ u64 shfx(u64 a, int m) {
    float l, h; upk(a, l, h);
    return pk(__shfl_xor_sync(FULL, l, m), __shfl_xor_sync(FULL, h, m));
}
__device__ __forceinline__ u64 shfi(u64 a, int s) {
    float l, h; upk(a, l, h);
    return pk(__shfl_sync(FULL, l, s), __shfl_sync(FULL, h, s));
}

// Per gate (layer*8+wire): fused weight matrix C = Rz*Ry*Rx (SU(2) first row):
// (C00r, C00i, C01r, C01i)
__device__ float4 g_Gf[48];

__global__ void precompute_G(const float* __restrict__ w) {
    int tid = threadIdx.x;
    if (tid >= 48) return;
    float c0, s0, c1, s1, cz, sz;
    sincosf(0.5f * w[tid * 3 + 0], &s0, &c0);   // Rx
    sincosf(0.5f * w[tid * 3 + 1], &s1, &c1);   // Ry
    sincosf(0.5f * w[tid * 3 + 2], &sz, &cz);   // Rz
    float A00r = c1 * c0,  A00i = s1 * s0;
    float A01r = -s1 * c0, A01i = -c1 * s0;
    float C00r = cz * A00r + sz * A00i;
    float C00i = cz * A00i - sz * A00r;
    float C01r = cz * A01r + sz * A01i;
    float C01i = cz * A01i - sz * A01r;
    g_Gf[tid] = make_float4(C00r, C00i, C01r, C01i);
}

// One warp per batch element. Amplitude n: lane bits 4..0 = n bits 7..3
// (wires 0..4), reg index t bits 2..0 = n bits 2..0 (wires 5,6,7).
// State packed SoA along t-bit0 (wire7): pr[j]=(re[2j],re[2j+1]), pi[j] same.
__global__ void __launch_bounds__(128, 10) qnn_kernel(const float* __restrict__ x,
                                                      float* __restrict__ out, int B) {
    __shared__ float4 sG[48];
    if (threadIdx.x < 48) sG[threadIdx.x] = g_Gf[threadIdx.x];
    __syncthreads();

    int warp = (blockIdx.x * blockDim.x + threadIdx.x) >> 5;
    int lane = threadIdx.x & 31;
    if (warp >= B) return;

    float se, ce, so, co;
    __sincosf(0.5f * x[2 * warp + 0], &se, &ce);  // RX enc (even wires)
    __sincosf(0.5f * x[2 * warp + 1], &so, &co);  // RY enc (odd wires)
    u64 ce2 = pk2(ce), se2 = pk2(se), co2 = pk2(co), so2 = pk2(so), nso2 = pk2(-so);

    // Fused gate matrix M = C*E(x): packed m00=(m00r,m00i), m01=(m01r,m01i).
#define GATE_M(g, wire, m00p, m01p)                                        \
    {                                                                      \
        float4 Cg = sG[g];                                                 \
        u64 Gx = pk(Cg.x, Cg.y);   /* (C00r,C00i) */                       \
        u64 Gy = pk(Cg.z, Cg.w);   /* (C01r,C01i) */                       \
        u64 Gz = pk(Cg.w, -Cg.z);  /* (C01i,-C01r) */                      \
        u64 Gw = pk(Cg.y, -Cg.x);  /* (C00i,-C00r) */                      \
        if (((wire) & 1) == 0) {   /* RX */                                \
            m00p = fma2(ce2, Gx, mul2(se2, Gz));                           \
            m01p = fma2(ce2, Gy, mul2(se2, Gw));                           \
        } else {                   /* RY */                                \
            m00p = fma2(co2, Gx, mul2(so2, Gy));                           \
            m01p = fma2(co2, Gy, mul2(nso2, Gx));                          \
        }                                                                  \
    }

    u64 pr[4], pi[4];

    // ---------- layer 0: product state built directly from |0..0> ----------
    {
        float g0r[8], g0i[8], g1r[8], g1i[8];   // column 0: m00 and m10=-conj(m01)
#pragma unroll
        for (int wv = 0; wv < 8; wv++) {
            u64 m00p, m01p;
            GATE_M(wv, wv, m00p, m01p);
            float r0, i0, r1, i1;
            upk(m00p, r0, i0); upk(m01p, r1, i1);
            g0r[wv] = r0;  g0i[wv] = i0;
            g1r[wv] = -r1; g1i[wv] = i1;
        }
        float cr = 1.f, ci = 0.f;
#pragma unroll
        for (int wv = 0; wv < 5; wv++) {
            bool b = (lane >> (4 - wv)) & 1;
            float fr = b ? g1r[wv] : g0r[wv];
            float fi = b ? g1i[wv] : g0i[wv];
            float nr = cr * fr - ci * fi;
            float ni = cr * fi + ci * fr;
            cr = nr; ci = ni;
        }
        float ar[8], ai[8];
        {
            float d0r = cr * g0r[5] - ci * g0i[5], d0i = cr * g0i[5] + ci * g0r[5];
            float d1r = cr * g1r[5] - ci * g1i[5], d1i = cr * g1i[5] + ci * g1r[5];
            float e0r[4], e0i[4];
            e0r[0] = d0r * g0r[6] - d0i * g0i[6]; e0i[0] = d0r * g0i[6] + d0i * g0r[6];
            e0r[1] = d0r * g1r[6] - d0i * g1i[6]; e0i[1] = d0r * g1i[6] + d0i * g1r[6];
            e0r[2] = d1r * g0r[6] - d1i * g0i[6]; e0i[2] = d1r * g0i[6] + d1i * g0r[6];
            e0r[3] = d1r * g1r[6] - d1i * g1i[6]; e0i[3] = d1r * g1i[6] + d1i * g1r[6];
#pragma unroll
            for (int t = 0; t < 8; t++) {
                int e = t >> 1;
                bool b7 = t & 1;
                float fr = b7 ? g1r[7] : g0r[7];
                float fi = b7 ? g1i[7] : g0i[7];
                ar[t] = e0r[e] * fr - e0i[e] * fi;
                ai[t] = e0r[e] * fi + e0i[e] * fr;
            }
        }
#pragma unroll
        for (int j = 0; j < 4; j++) {
            pr[j] = pk(ar[2 * j], ar[2 * j + 1]);
            pi[j] = pk(ai[2 * j], ai[2 * j + 1]);
        }
    }

    // lane permutation source for the composed CNOT(0,1)..CNOT(3,4) chain
    int src = lane;
    src ^= (src >> 1) & 1;
    src ^= (src >> 1) & 2;
    src ^= (src >> 1) & 4;
    src ^= (src >> 1) & 8;
    const bool ctl45 = (lane & 1) != 0;

    // layer-0 CNOT chain + layers 1..5 (gates + CNOTs)
#pragma unroll
    for (int layer = 0; layer < 6; layer++) {
        if (layer > 0) {
#pragma unroll
            for (int wire = 0; wire < 8; wire++) {
                u64 m00p, m01p;
                GATE_M(layer * 8 + wire, wire, m00p, m01p);
                float m00r, m00i, m01r, m01i;
                upk(m00p, m00r, m00i); upk(m01p, m01r, m01i);

                if (wire < 5) {
                    // lane-level butterfly via shfl.xor
                    const int lm = 1 << (4 - wire);
                    bool neg = (lane & lm) != 0;
                    float Piv = neg ? -m00i : m00i;
                    float Qrv = neg ? -m01r : m01r;
                    u64 Pr2 = pk2(m00r), Pi2 = pk2(Piv), nPi2 = pk2(-Piv);
                    u64 Qr2 = pk2(Qrv), Qi2 = pk2(m01i), nQi2 = pk2(-m01i);
#pragma unroll
                    for (int j = 0; j < 4; j++) {
                        u64 opr = shfx(pr[j], lm);
                        u64 opi = shfx(pi[j], lm);
                        u64 nr = fma2(Pr2, pr[j], fma2(nPi2, pi[j], fma2(Qr2, opr, mul2(nQi2, opi))));
                        u64 ni = fma2(Pi2, pr[j], fma2(Pr2, pi[j], fma2(Qi2, opr, mul2(Qr2, opi))));
                        pr[j] = nr; pi[j] = ni;
                    }
                } else if (wire < 7) {
                    // inter-register packed butterfly (wire5: stride 2; wire6: stride 1)
                    u64 r00 = pk2(m00r), i00 = pk2(m00i), ni00 = pk2(-m00i);
                    u64 r01 = pk2(m01r), nr01 = pk2(-m01r), i01 = pk2(m01i), ni01 = pk2(-m01i);
                    const int off = (wire == 5) ? 2 : 1;
#pragma unroll
                    for (int j = 0; j < 4; j++) {
                        if (j & off) continue;
                        int k = j | off;
                        u64 pA = pr[j], qA = pi[j], pB = pr[k], qB = pi[k];
                        pr[j] = fma2(r00, pA, fma2(ni00, qA, fma2(r01, pB, mul2(ni01, qB))));
                        pi[j] = fma2(i00, pA, fma2(r00, qA, fma2(i01, pB, mul2(r01, qB))));
                        pr[k] = fma2(nr01, pA, fma2(ni01, qA, fma2(r00, pB, mul2(i00, qB))));
                        pi[k] = fma2(i01, pA, fma2(nr01, qA, fma2(ni00, pB, mul2(r00, qB))));
                    }
                } else {
                    // wire7: intra-register butterfly with half-swaps
                    u64 A = pk2(m00r);
                    u64 Bc = pk(m01r, -m01r);
                    u64 Cc = pk(-m00i, m00i);
                    u64 D = pk2(-m01i);
                    u64 E = pk(m00i, -m00i);
                    u64 F = pk2(m01i);
#pragma unroll
                    for (int j = 0; j < 4; j++) {
                        u64 spr = swp(pr[j]), spi = swp(pi[j]);
                        u64 nr = fma2(A, pr[j], fma2(Bc, spr, fma2(Cc, pi[j], mul2(D, spi))));
                        u64 ni = fma2(E, pr[j], fma2(F, spr, fma2(A, pi[j], mul2(Bc, spi))));
                        pr[j] = nr; pi[j] = ni;
                    }
                }
            }
        }

        // ---- CNOT chain ----
        // CNOT(0,1)..CNOT(3,4): composed lane permutation
#pragma unroll
        for (int j = 0; j < 4; j++) {
            pr[j] = shfi(pr[j], src);
            pi[j] = shfi(pi[j], src);
        }
        // CNOT(4,5): control lane bit0, target reg bit2
#pragma unroll
        for (int k = 0; k < 2; k++) {
            u64 a = pr[k], b = pr[k + 2];
            pr[k] = ctl45 ? b : a; pr[k + 2] = ctl45 ? a : b;
            u64 c = pi[k], d = pi[k + 2];
            pi[k] = ctl45 ? d : c; pi[k + 2] = ctl45 ? c : d;
        }
        // CNOT(5,6): swap reg pair 2<->3 (t: 4<->6, 5<->7)  [free rename — loop unrolled]
        {
            u64 t;
            t = pr[2]; pr[2] = pr[3]; pr[3] = t;
            t = pi[2]; pi[2] = pi[3]; pi[3] = t;
        }
        // CNOT(6,7): swap halves of regs 1 and 3 (t: 2<->3, 6<->7)
        pr[1] = swp(pr[1]); pr[3] = swp(pr[3]);
        pi[1] = swp(pi[1]); pi[3] = swp(pi[3]);
    }

    // ---------- expectation values ----------
    float p[8];
#pragma unroll
    for (int j = 0; j < 4; j++) {
        u64 pp = fma2(pr[j], pr[j], mul2(pi[j], pi[j]));
        upk(pp, p[2 * j], p[2 * j + 1]);
    }

    float ev[8];
    float tot = ((p[0] + p[1]) + (p[2] + p[3])) + ((p[4] + p[5]) + (p[6] + p[7]));
#pragma unroll
    for (int i = 0; i < 5; i++)
        ev[i] = (lane & (1 << (4 - i))) ? -tot : tot;
    ev[5] = (p[0] + p[1] + p[2] + p[3]) - (p[4] + p[5] + p[6] + p[7]);
    ev[6] = (p[0] + p[1] + p[4] + p[5]) - (p[2] + p[3] + p[6] + p[7]);
    ev[7] = (p[0] + p[2] + p[4] + p[6]) - (p[1] + p[3] + p[5] + p[7]);

#pragma unroll
    for (int off = 16; off > 0; off >>= 1) {
#pragma unroll
        for (int i = 0; i < 8; i++)
            ev[i] += __shfl_xor_sync(FULL, ev[i], off);
    }

    if (lane == 0) {
        const float PI = 3.14159265358979f;
        ((float4*)out)[warp * 2 + 0] = make_float4(ev[0] * PI, ev[1] * PI, ev[2] * PI, ev[3] * PI);
        ((float4*)out)[warp * 2 + 1] = make_float4(ev[4] * PI, ev[5] * PI, ev[6] * PI, ev[7] * PI);
    }
#undef GATE_M
}

extern "C" void kernel_launch(void* const* d_in, const int* in_sizes, int n_in,
                              void* d_out, int out_size) {
    const float* x = (const float*)d_in[0];   // [B, 2]
    const float* w = (const float*)d_in[1];   // [6, 8, 3]
    float* out = (float*)d_out;               // [B, 8]
    int B = in_sizes[0] / 2;

    precompute_G<<<1, 64>>>(w);
    int threads = 128;
    int blocks = (B * 32 + threads - 1) / threads;
    qnn_kernel<<<blocks, threads>>>(x, out, B);
}